// round 13
// baseline (speedup 1.0000x reference)
#include <cuda_runtime.h>
#include <cuda_fp16.h>
#include <math.h>
#include <stdint.h>

#define MTOT 8192
#define DF   768
#define KD   64
#define HW   1024
#define BSZ  8
#define NEDGE (MTOT * 32)

// ---------------- scratch (device globals; no allocation) ----------------
__device__ uint4 g_Xhi4[MTOT * DF / 8];            // fp16 hi parts (x*32)
__device__ uint4 g_Xlo4[MTOT * DF / 8];            // fp16 lo parts
__device__ float g_S[(size_t)MTOT * MTOT];         // 256 MB similarity matrix
__device__ float g_Psi[MTOT * KD];
__device__ float g_topv[NEDGE];
__device__ int   g_topi[NEDGE];
__device__ float g_rowsumA[MTOT];
__device__ float g_Dinv[MTOT];
__device__ unsigned char g_A2[(size_t)MTOT * HW];
__device__ float g_D2inv[MTOT];
__device__ float g_gP[MTOT * KD];
__device__ float g_R[KD * KD];
__device__ int   g_tcnt[MTOT];
__device__ int   g_toff[MTOT + 1];
__device__ int   g_tfill[MTOT];
__device__ int   g_tadj[NEDGE];

// ---------------- helpers ----------------
__device__ __forceinline__ uint32_t smem_u32(const void* p) {
    uint32_t a;
    asm("{ .reg .u64 t; cvta.to.shared.u64 t, %1; cvt.u32.u64 %0, t; }" : "=r"(a) : "l"(p));
    return a;
}
#define SWZ(o) ((o) ^ (((o) >> 3) & 0x70))

__device__ __forceinline__ void ldmx4(uint32_t* r, uint32_t addr) {
    asm volatile("ldmatrix.sync.aligned.m8n8.x4.shared.b16 {%0,%1,%2,%3}, [%4];"
                 : "=r"(r[0]), "=r"(r[1]), "=r"(r[2]), "=r"(r[3]) : "r"(addr));
}
__device__ __forceinline__ void mma_f16(float* d, const uint32_t* a, uint32_t b0, uint32_t b1) {
    asm volatile(
        "mma.sync.aligned.m16n8k16.row.col.f32.f16.f16.f32 "
        "{%0,%1,%2,%3}, {%4,%5,%6,%7}, {%8,%9}, {%0,%1,%2,%3};"
        : "+f"(d[0]), "+f"(d[1]), "+f"(d[2]), "+f"(d[3])
        : "r"(a[0]), "r"(a[1]), "r"(a[2]), "r"(a[3]), "r"(b0), "r"(b1));
}
__device__ __forceinline__ void cp_async16(uint32_t dst, const void* src) {
    asm volatile("cp.async.cg.shared.global [%0], [%1], 16;" :: "r"(dst), "l"(src));
}
#define CP_COMMIT() asm volatile("cp.async.commit_group;" ::: "memory")
#define CP_WAIT(n)  asm volatile("cp.async.wait_group %0;" :: "n"(n) : "memory")

// GEMM (R8 tiling): CTA 128x128, 8 warps 2(M)x4(N), warp tile 64x32, K-chunk 32.
// fp16 3-product split (x scaled by 32): S*1024 = hi*hi + lo*hi + hi*lo
// Stage = 4 tiles (Ahi,Alo,Bhi,Blo) x 8KB = 32KB; 3 stages = 96KB; 2 CTAs/SM.
#define STG        32768
#define SMEM_TOTAL (3 * STG)
#define TS_PAD     68
#define NCHUNK     (DF / 32)   // 24

// ---------------- zero scratch + psi scale (merged) ----------------
__global__ void prep_kernel(const float* __restrict__ psi) {
    int idx = blockIdx.x * blockDim.x + threadIdx.x;
    int stride = gridDim.x * blockDim.x;
    for (int i = idx; i < MTOT; i += stride) { g_rowsumA[i] = 0.f; g_tcnt[i] = 0; }
    for (int i = idx; i < KD * KD; i += stride) g_R[i] = 0.f;
    for (int i = idx; i < MTOT * KD; i += stride)
        g_Psi[i] = psi[i] * 3.16227766016837933f;   // sqrt(10)
    unsigned int* a2 = (unsigned int*)g_A2;
    for (int i = idx; i < (MTOT * HW) >> 2; i += stride) a2[i] = 0u;
}

// ---------------- row L2-normalize + scaled fp16 hi/lo split ----------------
__global__ __launch_bounds__(256) void norm_kernel(const float* __restrict__ hf) {
    int row = blockIdx.x;
    const float* x = hf + (size_t)row * DF;
    int tid = threadIdx.x;
    float s = 0.f;
    for (int d = tid; d < DF; d += 256) { float v = x[d]; s += v * v; }
#pragma unroll
    for (int o = 16; o; o >>= 1) s += __shfl_xor_sync(0xffffffffu, s, o);
    __shared__ float red[8];
    if ((tid & 31) == 0) red[tid >> 5] = s;
    __syncthreads();
    float tot = red[0] + red[1] + red[2] + red[3] + red[4] + red[5] + red[6] + red[7];
    float inv = 32.0f / sqrtf(tot);            // x * 32 (avoids fp16 denormal lo)
    __half* hi = (__half*)g_Xhi4;
    __half* lo = (__half*)g_Xlo4;
    for (int d = tid; d < DF; d += 256) {
        float v = x[d] * inv;
        __half h = __float2half_rn(v);
        float hr = __half2float(h);
        hi[(size_t)row * DF + d] = h;
        lo[(size_t)row * DF + d] = __float2half_rn(v - hr);
    }
}

// ---------------- HMMA GEMM: S = Xn Xn^T (proven R8/R11 form) ----------------
__global__ __launch_bounds__(256, 2) void gemm_mma_kernel() {
    int bi = blockIdx.y << 7;
    int bj = blockIdx.x << 7;
    if (bj < bi) return;                       // symmetry: upper block triangle only
    extern __shared__ __align__(1024) char smem[];
    uint32_t sb = smem_u32(smem);
    int tid = threadIdx.x;
    int wid = tid >> 5, lid = tid & 31;
    int wm = wid >> 2, wn = wid & 3;           // warp grid 2(M) x 4(N), tile 64x32

    float acc[4][4][4];
#pragma unroll
    for (int mt = 0; mt < 4; mt++)
#pragma unroll
        for (int nt = 0; nt < 4; nt++)
#pragma unroll
            for (int d = 0; d < 4; d++) acc[mt][nt][d] = 0.f;

    int arow = lid & 15, acb = lid >> 4;
    int brow = (lid >= 16 ? 8 : 0) + (lid & 7);
    int bcb = (lid >> 3) & 1;

    auto rpoff = [](int row, int c16) -> uint32_t {
        uint32_t o = (uint32_t)((row >> 1) * 128 + (row & 1) * 64 + c16 * 16);
        return SWZ(o);
    };

    auto load_chunk = [&](int c, int buf) {
        uint32_t base = sb + buf * STG;
#pragma unroll
        for (int i = 0; i < 8; i++) {
            int id = i * 256 + tid;            // 0..2047
            int t = id >> 9, rem = id & 511;   // tile, then 128 rows x 4 cb
            int row = rem >> 2, cb = rem & 3;
            const uint4* gs = (t & 1) ? g_Xlo4 : g_Xhi4;
            int rb = (t < 2) ? bi : bj;
            cp_async16(base + t * 8192 + rpoff(row, cb),
                       gs + (size_t)(rb + row) * (DF / 8) + c * 4 + cb);
        }
        CP_COMMIT();
    };

    load_chunk(0, 0);
    load_chunk(1, 1);
#pragma unroll 1
    for (int c = 0; c < NCHUNK; c++) {
        if (c + 1 < NCHUNK) { CP_WAIT(1); } else { CP_WAIT(0); }
        __syncthreads();
        if (c + 2 < NCHUNK) load_chunk(c + 2, (c + 2) % 3);
        uint32_t st = sb + (c % 3) * STG;
        uint32_t Ahi = st, Alo = st + 8192, Bhi = st + 16384, Blo = st + 24576;
#pragma unroll
        for (int kk = 0; kk < 2; kk++) {
            int ac16 = kk * 2 + acb;
            int bc16 = kk * 2 + bcb;
            uint32_t ahf[4][4], bhf[2][4];
#pragma unroll
            for (int mt = 0; mt < 4; mt++)
                ldmx4(ahf[mt], Ahi + rpoff(wm * 64 + mt * 16 + arow, ac16));
#pragma unroll
            for (int pt = 0; pt < 2; pt++)
                ldmx4(bhf[pt], Bhi + rpoff(wn * 32 + pt * 16 + brow, bc16));
            // hi x hi
#pragma unroll
            for (int mt = 0; mt < 4; mt++)
#pragma unroll
                for (int nt = 0; nt < 4; nt++)
                    mma_f16(acc[mt][nt], ahf[mt],
                            bhf[nt >> 1][(nt & 1) * 2], bhf[nt >> 1][(nt & 1) * 2 + 1]);
            // lo x hi (reuse bhf)
            {
                uint32_t alf[4][4];
#pragma unroll
                for (int mt = 0; mt < 4; mt++)
                    ldmx4(alf[mt], Alo + rpoff(wm * 64 + mt * 16 + arow, ac16));
#pragma unroll
                for (int mt = 0; mt < 4; mt++)
#pragma unroll
                    for (int nt = 0; nt < 4; nt++)
                        mma_f16(acc[mt][nt], alf[mt],
                                bhf[nt >> 1][(nt & 1) * 2], bhf[nt >> 1][(nt & 1) * 2 + 1]);
            }
            // hi x lo (reuse ahf)
            {
                uint32_t blf[2][4];
#pragma unroll
                for (int pt = 0; pt < 2; pt++)
                    ldmx4(blf[pt], Blo + rpoff(wn * 32 + pt * 16 + brow, bc16));
#pragma unroll
                for (int mt = 0; mt < 4; mt++)
#pragma unroll
                    for (int nt = 0; nt < 4; nt++)
                        mma_f16(acc[mt][nt], ahf[mt],
                                blf[nt >> 1][(nt & 1) * 2], blf[nt >> 1][(nt & 1) * 2 + 1]);
            }
        }
    }
    __syncthreads();

    // epilogue in two 128x64 halves (reuse stage smem); rescale by 1/1024
    float* ts = (float*)smem;
    int qr = lid >> 2, qc = (lid & 3) * 2;
#pragma unroll 1
    for (int h = 0; h < 2; h++) {
        if ((wn >> 1) == h) {
#pragma unroll
            for (int mt = 0; mt < 4; mt++)
#pragma unroll
                for (int nt = 0; nt < 4; nt++)
#pragma unroll
                    for (int d = 0; d < 4; d++) {
                        int r = wm * 64 + mt * 16 + qr + (d >> 1) * 8;
                        int lc = (wn & 1) * 32 + nt * 8 + qc + (d & 1);
                        float v = fmaxf(acc[mt][nt][d] * 9.765625e-4f, 0.f);
                        if (bi + r == bj + h * 64 + lc) v = 0.f;
                        ts[r * TS_PAD + lc] = v;
                    }
        }
        __syncthreads();
        {   // direct: 128 rows x 64 cols
            int r = tid >> 1, seg = tid & 1;
            const float4* src = (const float4*)(ts + r * TS_PAD + seg * 32);
            float4* dst = (float4*)(g_S + (size_t)(bi + r) * MTOT + bj + h * 64 + seg * 32);
#pragma unroll
            for (int k = 0; k < 8; k++) dst[k] = src[k];
        }
        {   // mirror: 64 cols -> rows (transposed read)
            int cc = tid >> 2, q = (tid & 3) * 32;
            float4* dst = (float4*)(g_S + (size_t)(bj + h * 64 + cc) * MTOT + bi + q);
#pragma unroll
            for (int k = 0; k < 8; k++) {
                int rr = q + k * 4;
                dst[k] = make_float4(ts[(rr + 0) * TS_PAD + cc], ts[(rr + 1) * TS_PAD + cc],
                                     ts[(rr + 2) * TS_PAD + cc], ts[(rr + 3) * TS_PAD + cc]);
            }
        }
        __syncthreads();
    }
}

// ---------------- top-32: 2 rows per block, shared barrier rounds ----------------
__global__ __launch_bounds__(512) void topk_kernel() {
    int sub = threadIdx.x >> 8;                // 0 or 1: which row of this block
    int tid = threadIdx.x & 255;               // index within sub-block
    int row = (blockIdx.x << 1) + sub;
    int w8 = tid >> 5;                         // warp within sub (0..7)
    int lane = threadIdx.x & 31;
    const float4* Sr4 = (const float4*)(g_S + (size_t)row * MTOT);
    unsigned int v[32];
#pragma unroll
    for (int k = 0; k < 8; k++) {
        float4 f = Sr4[tid + (k << 8)];
        v[4 * k + 0] = __float_as_uint(f.x);
        v[4 * k + 1] = __float_as_uint(f.y);
        v[4 * k + 2] = __float_as_uint(f.z);
        v[4 * k + 3] = __float_as_uint(f.w);
    }
    __shared__ int wc[2][2][8];
    __shared__ int slist_n[2], s_pos[2];
    __shared__ unsigned int skth[2];
    __shared__ unsigned int lval[2][2048];
    __shared__ int lidx[2][2048];
    if (tid == 0) { slist_n[sub] = 0; s_pos[sub] = 0; }
    __syncthreads();
    // coarse bin floor: bits 29..22, barriers shared between both rows
    unsigned int kth = 0;
    for (int bit = 29; bit >= 22; bit--) {
        unsigned int cand = kth | (1u << bit);
        int c = 0;
#pragma unroll
        for (int k = 0; k < 32; k++) c += (v[k] >= cand) ? 1 : 0;
        int wsum = __reduce_add_sync(0xffffffffu, c);
        if (lane == 0) wc[sub][bit & 1][w8] = wsum;
        __syncthreads();
        const int* q = wc[sub][bit & 1];
        int tot = q[0] + q[1] + q[2] + q[3] + q[4] + q[5] + q[6] + q[7];
        if (tot >= 32) kth = cand;
    }
    // compact candidates >= bin floor from registers
#pragma unroll
    for (int k = 0; k < 32; k++) {
        if (v[k] >= kth) {
            int p = atomicAdd(&slist_n[sub], 1);
            if (p < 2048) {
                lval[sub][p] = v[k];
                lidx[sub][p] = 4 * tid + (k >> 2) * 1024 + (k & 3);
            }
        }
    }
    __syncthreads();
    int n = min(slist_n[sub], 2048);
    if (w8 == 0) {                             // warp 0 of each sub refines concurrently
        unsigned int kf = kth;
        if (n <= 256) {
            unsigned int cach[8];
#pragma unroll
            for (int q = 0; q < 8; q++) {
                int e = lane + q * 32;
                cach[q] = (e < n) ? lval[sub][e] : 0u;
            }
            for (int bit = 21; bit >= 0; bit--) {
                unsigned int cand = kf | (1u << bit);
                int c = 0;
#pragma unroll
                for (int q = 0; q < 8; q++) c += (cach[q] >= cand) ? 1 : 0;
                c = __reduce_add_sync(0xffffffffu, c);
                if (c >= 32) kf = cand;
            }
        } else {
            for (int bit = 21; bit >= 0; bit--) {
                unsigned int cand = kf | (1u << bit);
                int c = 0;
                for (int e = lane; e < n; e += 32) c += (lval[sub][e] >= cand) ? 1 : 0;
                c = __reduce_add_sync(0xffffffffu, c);
                if (c >= 32) kf = cand;
            }
        }
        if (lane == 0) skth[sub] = kf;
    }
    __syncthreads();
    unsigned int kf = skth[sub];
    for (int e = tid; e < n; e += 256) {
        if (lval[sub][e] >= kf) {
            int p = atomicAdd(&s_pos[sub], 1);
            if (p < 32) {
                int j = lidx[sub][e];
                float fv = __uint_as_float(lval[sub][e]);
                g_topi[(row << 5) + p] = j;
                g_topv[(row << 5) + p] = fv;
                atomicAdd(&g_rowsumA[j], 0.5f * fv);
                atomicAdd(&g_rowsumA[row], 0.5f * fv);
                atomicAdd(&g_tcnt[j], 1);
            }
        }
    }
}

// ---------------- exclusive scan of transpose counts (1 block) ----------------
__global__ __launch_bounds__(1024) void scan_kernel() {
    __shared__ int ssum[1024];
    int tid = threadIdx.x;
    int local[8], s = 0;
#pragma unroll
    for (int k = 0; k < 8; k++) { local[k] = g_tcnt[tid * 8 + k]; s += local[k]; }
    ssum[tid] = s;
    __syncthreads();
    int acc = s;
    for (int off = 1; off < 1024; off <<= 1) {
        int vv = (tid >= off) ? ssum[tid - off] : 0;
        __syncthreads();
        acc += vv;
        ssum[tid] = acc;
        __syncthreads();
    }
    int run = acc - s;
#pragma unroll
    for (int k = 0; k < 8; k++) {
        g_toff[tid * 8 + k] = run;
        g_tfill[tid * 8 + k] = run;
        run += local[k];
    }
    if (tid == 1023) g_toff[MTOT] = run;
}

__global__ void fill_kernel() {
    int idx = blockIdx.x * 256 + threadIdx.x;
    int j = g_topi[idx];
    int pos = atomicAdd(&g_tfill[j], 1);
    g_tadj[pos] = idx;
}

// ---------------- pixel kNN: one warp per pixel ----------------
__global__ __launch_bounds__(256) void pixknn_kernel(const float* __restrict__ im) {
    int w = threadIdx.x >> 5, lane = threadIdx.x & 31;
    int p = blockIdx.x * 8 + w;
    int cfg = blockIdx.y;
    int b = blockIdx.z;
    float dw = (cfg == 0) ? 2.0f : 0.1f;
    __shared__ float sR[HW], sG[HW], sB[HW], sX[HW], sY[HW], sQ[HW];
    int tid = threadIdx.x;
    const float* imb = im + (size_t)b * 3 * HW;
    for (int q = tid; q < HW; q += 256) {
        float r = (imb[q] + 1.f) * 0.5f;
        float g = (imb[HW + q] + 1.f) * 0.5f;
        float bl = (imb[2 * HW + q] + 1.f) * 0.5f;
        float x = ((float)(q & 31) / 31.0f) * dw;
        float y = ((float)(q >> 5) / 31.0f) * dw;
        sR[q] = r; sG[q] = g; sB[q] = bl; sX[q] = x; sY[q] = y;
        sQ[q] = r * r + g * g + bl * bl + x * x + y * y;
    }
    __syncthreads();
    float rp = sR[p], gp = sG[p], bp = sB[p], xp = sX[p], yp = sY[p], qp = sQ[p];
    unsigned int key[32];
#pragma unroll
    for (int k = 0; k < 32; k++) {
        int q = lane + (k << 5);
        float dot = rp * sR[q] + gp * sG[q] + bp * sB[q] + xp * sX[q] + yp * sY[q];
        float d2 = fmaxf(qp + sQ[q] - 2.f * dot, 0.f);
        key[k] = (q == p) ? 0x7F800000u : __float_as_uint(d2);
    }
    unsigned int s = 0;
    for (int bit = 30; bit >= 0; bit--) {
        unsigned int cand = s | (1u << bit);
        int c = 0;
#pragma unroll
        for (int k = 0; k < 32; k++) c += (key[k] < cand) ? 1 : 0;
        int tot = __reduce_add_sync(0xffffffffu, c);
        if (tot <= 9) s = cand;
    }
    size_t rbase = ((size_t)b * HW + p) * HW;
#pragma unroll
    for (int k = 0; k < 32; k++) {
        if (key[k] <= s) {
            int q = lane + (k << 5);
            g_A2[rbase + q] = 1;
            g_A2[((size_t)b * HW + q) * HW + p] = 1;
        }
    }
}

// ---------------- pixel degree + feature degree (merged) ----------------
__global__ __launch_bounds__(256) void d2_kernel() {
    int r = blockIdx.x;
    const unsigned int* row = (const unsigned int*)(g_A2 + (size_t)r * HW);
    int tid = threadIdx.x;
    unsigned int u = row[tid];
    int c = (u & 0xFF) + ((u >> 8) & 0xFF) + ((u >> 16) & 0xFF) + (u >> 24);
    int wsum = __reduce_add_sync(0xffffffffu, c);
    __shared__ int wc[8];
    if ((tid & 31) == 0) wc[tid >> 5] = wsum;
    __syncthreads();
    if (tid == 0) {
        int tot = wc[0] + wc[1] + wc[2] + wc[3] + wc[4] + wc[5] + wc[6] + wc[7];
        g_D2inv[r] = 1.0f / sqrtf((float)tot);
        g_Dinv[r] = 1.0f / sqrtf(g_rowsumA[r]);
    }
}

// ---------------- gram @ Psi: feature (gather CSR) + pixel, single write ----------------
__global__ __launch_bounds__(128) void gp_kernel() {
    int i = blockIdx.x;
    int b = i >> 10;
    int tid = threadIdx.x;
    int col = tid & 63, half = tid >> 6;
    __shared__ int sidx[512];
    __shared__ float sw[512];
    __shared__ float part[64];
    __shared__ int lst[1024];
    __shared__ int cnt;
    float dj = g_Dinv[i];
    if (tid < 32) {
        int t = g_topi[(i << 5) + tid];
        sidx[tid] = t;
        sw[tid] = 0.5f * g_topv[(i << 5) + tid] * dj * g_Dinv[t];
    }
    if (tid == 0) cnt = 0;
    __syncthreads();
    float facc = 0.f;
    for (int e = half; e < 32; e += 2) facc += sw[e] * g_Psi[sidx[e] * KD + col];
    __syncthreads();
    int start = g_toff[i], end = g_toff[i + 1];
    for (int ch = start; ch < end; ch += 512) {
        int n = min(512, end - ch);
        for (int k = tid; k < n; k += 128) {
            int idx = g_tadj[ch + k];
            int r2 = idx >> 5;
            sidx[k] = r2;
            sw[k] = 0.5f * g_topv[idx] * dj * g_Dinv[r2];
        }
        __syncthreads();
        for (int k = half; k < n; k += 2) facc += sw[k] * g_Psi[sidx[k] * KD + col];
        __syncthreads();
    }
    // pixel adjacency
    const unsigned char* row = g_A2 + (size_t)i * HW;
    for (int q = tid; q < HW; q += 128) {
        if (row[q]) { int pos = atomicAdd(&cnt, 1); lst[pos] = q; }
    }
    __syncthreads();
    int n2 = cnt;
    float w0 = 0.05f * g_D2inv[i];
    float pacc = 0.f;
    for (int e = half; e < n2; e += 2) {
        int gq = (b << 10) + lst[e];
        pacc += g_D2inv[gq] * g_Psi[gq * KD + col];
    }
    float tot = facc + pacc * w0;
    if (half) part[col] = tot;
    __syncthreads();
    if (!half) g_gP[i * KD + col] = tot + part[col];
}

// ---------------- R = Psi_s^T @ gP ----------------
__global__ __launch_bounds__(256) void r_kernel() {
    __shared__ float sp[64][KD];
    __shared__ float sg[64][KD];
    int i0 = blockIdx.x * 64;
    int tid = threadIdx.x;
    for (int e = tid; e < 64 * KD; e += 256) {
        sp[e >> 6][e & 63] = g_Psi[(i0 + (e >> 6)) * KD + (e & 63)];
        sg[e >> 6][e & 63] = g_gP[(i0 + (e >> 6)) * KD + (e & 63)];
    }
    __syncthreads();
    int a = tid >> 2;
    int c0 = (tid & 3) << 4;
    float acc[16];
#pragma unroll
    for (int u = 0; u < 16; u++) acc[u] = 0.f;
    for (int ii = 0; ii < 64; ii++) {
        float pa = sp[ii][a];
#pragma unroll
        for (int u = 0; u < 16; u++) acc[u] += pa * sg[ii][c0 + u];
    }
#pragma unroll
    for (int u = 0; u < 16; u++) atomicAdd(&g_R[a * KD + c0 + u], acc[u]);
}

// ---------------- loss & reg ----------------
__global__ __launch_bounds__(64) void final_kernel(float* __restrict__ out) {
    int tid = threadIdx.x;
    float tr = 0.f, rg = 0.f;
    for (int e = tid; e < KD * KD; e += 64) {
        float v = g_R[e];
        int a = e >> 6, b = e & 63;
        if (a == b) tr += v;
        if (b > a) rg += v * v;
    }
#pragma unroll
    for (int o = 16; o; o >>= 1) {
        tr += __shfl_xor_sync(0xffffffffu, tr, o);
        rg += __shfl_xor_sync(0xffffffffu, rg, o);
    }
    __shared__ float st[2], sr2[2];
    if ((tid & 31) == 0) { st[tid >> 5] = tr; sr2[tid >> 5] = rg; }
    __syncthreads();
    if (tid == 0) {
        out[0] = -(st[0] + st[1]) / 64.0f;
        out[1] = (sr2[0] + sr2[1]) / 64.0f;
    }
}

extern "C" void kernel_launch(void* const* d_in, const int* in_sizes, int n_in,
                              void* d_out, int out_size) {
    const float* hf = (const float*)d_in[0];   // (8,1024,768)
    const float* psi = (const float*)d_in[1];  // (8,1024,64)
    const float* im = (const float*)d_in[2];   // (8,3,32,32)
    float* out = (float*)d_out;

    cudaFuncSetAttribute(gemm_mma_kernel, cudaFuncAttributeMaxDynamicSharedMemorySize,
                         SMEM_TOTAL);

    prep_kernel<<<2048, 256>>>(psi);
    norm_kernel<<<MTOT, 256>>>(hf);

    dim3 g(MTOT / 128, MTOT / 128);
    gemm_mma_kernel<<<g, 256, SMEM_TOTAL>>>();

    topk_kernel<<<MTOT / 2, 512>>>();
    scan_kernel<<<1, 1024>>>();
    fill_kernel<<<NEDGE / 256, 256>>>();
    pixknn_kernel<<<dim3(HW / 8, 2, BSZ), 256>>>(im);
    d2_kernel<<<MTOT, 256>>>();

    gp_kernel<<<MTOT, 128>>>();

    r_kernel<<<MTOT / 64, 256>>>();
    final_kernel<<<1, 64>>>(out);
}

// round 14
// speedup vs baseline: 1.0495x; 1.0495x over previous
#include <cuda_runtime.h>
#include <cuda_fp16.h>
#include <math.h>
#include <stdint.h>

#define MTOT 8192
#define DF   768
#define KD   64
#define HW   1024
#define BSZ  8
#define NEDGE (MTOT * 32)

// ---------------- scratch (device globals; no allocation) ----------------
__device__ uint4 g_Xhi4[MTOT * DF / 8];            // fp16 hi parts (x*32)
__device__ uint4 g_Xlo4[MTOT * DF / 8];            // fp16 lo parts
__device__ float g_S[(size_t)MTOT * MTOT];         // 256 MB similarity matrix
__device__ float g_Psi[MTOT * KD];
__device__ float g_topv[NEDGE];
__device__ int   g_topi[NEDGE];
__device__ float g_rowsumA[MTOT];
__device__ float g_Dinv[MTOT];
__device__ unsigned char g_A2[(size_t)MTOT * HW];
__device__ float g_D2inv[MTOT];
__device__ float g_gP[MTOT * KD];
__device__ float g_R[KD * KD];
__device__ int   g_tcnt[MTOT];
__device__ int   g_toff[MTOT + 1];
__device__ int   g_tfill[MTOT];
__device__ int   g_tadj[NEDGE];

// ---------------- helpers ----------------
__device__ __forceinline__ uint32_t smem_u32(const void* p) {
    uint32_t a;
    asm("{ .reg .u64 t; cvta.to.shared.u64 t, %1; cvt.u32.u64 %0, t; }" : "=r"(a) : "l"(p));
    return a;
}
#define SWZ(o) ((o) ^ (((o) >> 3) & 0x70))

__device__ __forceinline__ void ldmx4(uint32_t* r, uint32_t addr) {
    asm volatile("ldmatrix.sync.aligned.m8n8.x4.shared.b16 {%0,%1,%2,%3}, [%4];"
                 : "=r"(r[0]), "=r"(r[1]), "=r"(r[2]), "=r"(r[3]) : "r"(addr));
}
__device__ __forceinline__ void mma_f16(float* d, const uint32_t* a, uint32_t b0, uint32_t b1) {
    asm volatile(
        "mma.sync.aligned.m16n8k16.row.col.f32.f16.f16.f32 "
        "{%0,%1,%2,%3}, {%4,%5,%6,%7}, {%8,%9}, {%0,%1,%2,%3};"
        : "+f"(d[0]), "+f"(d[1]), "+f"(d[2]), "+f"(d[3])
        : "r"(a[0]), "r"(a[1]), "r"(a[2]), "r"(a[3]), "r"(b0), "r"(b1));
}
__device__ __forceinline__ void cp_async16(uint32_t dst, const void* src) {
    asm volatile("cp.async.cg.shared.global [%0], [%1], 16;" :: "r"(dst), "l"(src));
}
#define CP_COMMIT() asm volatile("cp.async.commit_group;" ::: "memory")
#define CP_WAIT(n)  asm volatile("cp.async.wait_group %0;" :: "n"(n) : "memory")

// GEMM (R8 tiling): CTA 128x128, 8 warps 2(M)x4(N), warp tile 64x32, K-chunk 32.
// fp16 3-product split (x scaled by 32): S*1024 = hi*hi + lo*hi + hi*lo
// Stage = 4 tiles (Ahi,Alo,Bhi,Blo) x 8KB = 32KB; 3 stages = 96KB; 2 CTAs/SM.
#define STG        32768
#define SMEM_TOTAL (3 * STG)
#define TS_PAD     68
#define NCHUNK     (DF / 32)   // 24

// ---------------- zero scratch + psi scale (merged) ----------------
__global__ void prep_kernel(const float* __restrict__ psi) {
    int idx = blockIdx.x * blockDim.x + threadIdx.x;
    int stride = gridDim.x * blockDim.x;
    for (int i = idx; i < MTOT; i += stride) { g_rowsumA[i] = 0.f; g_tcnt[i] = 0; }
    for (int i = idx; i < KD * KD; i += stride) g_R[i] = 0.f;
    for (int i = idx; i < MTOT * KD; i += stride)
        g_Psi[i] = psi[i] * 3.16227766016837933f;   // sqrt(10)
    unsigned int* a2 = (unsigned int*)g_A2;
    for (int i = idx; i < (MTOT * HW) >> 2; i += stride) a2[i] = 0u;
}

// ---------------- row L2-normalize + scaled fp16 hi/lo split ----------------
__global__ __launch_bounds__(256) void norm_kernel(const float* __restrict__ hf) {
    int row = blockIdx.x;
    const float* x = hf + (size_t)row * DF;
    int tid = threadIdx.x;
    float s = 0.f;
    for (int d = tid; d < DF; d += 256) { float v = x[d]; s += v * v; }
#pragma unroll
    for (int o = 16; o; o >>= 1) s += __shfl_xor_sync(0xffffffffu, s, o);
    __shared__ float red[8];
    if ((tid & 31) == 0) red[tid >> 5] = s;
    __syncthreads();
    float tot = red[0] + red[1] + red[2] + red[3] + red[4] + red[5] + red[6] + red[7];
    float inv = 32.0f / sqrtf(tot);            // x * 32 (avoids fp16 denormal lo)
    __half* hi = (__half*)g_Xhi4;
    __half* lo = (__half*)g_Xlo4;
    for (int d = tid; d < DF; d += 256) {
        float v = x[d] * inv;
        __half h = __float2half_rn(v);
        float hr = __half2float(h);
        hi[(size_t)row * DF + d] = h;
        lo[(size_t)row * DF + d] = __float2half_rn(v - hr);
    }
}

// ---------------- HMMA GEMM: S = Xn Xn^T (proven R8/R11 form) ----------------
__global__ __launch_bounds__(256, 2) void gemm_mma_kernel() {
    int bi = blockIdx.y << 7;
    int bj = blockIdx.x << 7;
    if (bj < bi) return;                       // symmetry: upper block triangle only
    extern __shared__ __align__(1024) char smem[];
    uint32_t sb = smem_u32(smem);
    int tid = threadIdx.x;
    int wid = tid >> 5, lid = tid & 31;
    int wm = wid >> 2, wn = wid & 3;           // warp grid 2(M) x 4(N), tile 64x32

    float acc[4][4][4];
#pragma unroll
    for (int mt = 0; mt < 4; mt++)
#pragma unroll
        for (int nt = 0; nt < 4; nt++)
#pragma unroll
            for (int d = 0; d < 4; d++) acc[mt][nt][d] = 0.f;

    int arow = lid & 15, acb = lid >> 4;
    int brow = (lid >= 16 ? 8 : 0) + (lid & 7);
    int bcb = (lid >> 3) & 1;

    auto rpoff = [](int row, int c16) -> uint32_t {
        uint32_t o = (uint32_t)((row >> 1) * 128 + (row & 1) * 64 + c16 * 16);
        return SWZ(o);
    };

    auto load_chunk = [&](int c, int buf) {
        uint32_t base = sb + buf * STG;
#pragma unroll
        for (int i = 0; i < 8; i++) {
            int id = i * 256 + tid;            // 0..2047
            int t = id >> 9, rem = id & 511;   // tile, then 128 rows x 4 cb
            int row = rem >> 2, cb = rem & 3;
            const uint4* gs = (t & 1) ? g_Xlo4 : g_Xhi4;
            int rb = (t < 2) ? bi : bj;
            cp_async16(base + t * 8192 + rpoff(row, cb),
                       gs + (size_t)(rb + row) * (DF / 8) + c * 4 + cb);
        }
        CP_COMMIT();
    };

    load_chunk(0, 0);
    load_chunk(1, 1);
#pragma unroll 1
    for (int c = 0; c < NCHUNK; c++) {
        if (c + 1 < NCHUNK) { CP_WAIT(1); } else { CP_WAIT(0); }
        __syncthreads();
        if (c + 2 < NCHUNK) load_chunk(c + 2, (c + 2) % 3);
        uint32_t st = sb + (c % 3) * STG;
        uint32_t Ahi = st, Alo = st + 8192, Bhi = st + 16384, Blo = st + 24576;
#pragma unroll
        for (int kk = 0; kk < 2; kk++) {
            int ac16 = kk * 2 + acb;
            int bc16 = kk * 2 + bcb;
            uint32_t ahf[4][4], bhf[2][4];
#pragma unroll
            for (int mt = 0; mt < 4; mt++)
                ldmx4(ahf[mt], Ahi + rpoff(wm * 64 + mt * 16 + arow, ac16));
#pragma unroll
            for (int pt = 0; pt < 2; pt++)
                ldmx4(bhf[pt], Bhi + rpoff(wn * 32 + pt * 16 + brow, bc16));
            // hi x hi
#pragma unroll
            for (int mt = 0; mt < 4; mt++)
#pragma unroll
                for (int nt = 0; nt < 4; nt++)
                    mma_f16(acc[mt][nt], ahf[mt],
                            bhf[nt >> 1][(nt & 1) * 2], bhf[nt >> 1][(nt & 1) * 2 + 1]);
            // lo x hi (reuse bhf)
            {
                uint32_t alf[4][4];
#pragma unroll
                for (int mt = 0; mt < 4; mt++)
                    ldmx4(alf[mt], Alo + rpoff(wm * 64 + mt * 16 + arow, ac16));
#pragma unroll
                for (int mt = 0; mt < 4; mt++)
#pragma unroll
                    for (int nt = 0; nt < 4; nt++)
                        mma_f16(acc[mt][nt], alf[mt],
                                bhf[nt >> 1][(nt & 1) * 2], bhf[nt >> 1][(nt & 1) * 2 + 1]);
            }
            // hi x lo (reuse ahf)
            {
                uint32_t blf[2][4];
#pragma unroll
                for (int pt = 0; pt < 2; pt++)
                    ldmx4(blf[pt], Blo + rpoff(wn * 32 + pt * 16 + brow, bc16));
#pragma unroll
                for (int mt = 0; mt < 4; mt++)
#pragma unroll
                    for (int nt = 0; nt < 4; nt++)
                        mma_f16(acc[mt][nt], ahf[mt],
                                blf[nt >> 1][(nt & 1) * 2], blf[nt >> 1][(nt & 1) * 2 + 1]);
            }
        }
    }
    __syncthreads();

    // epilogue in two 128x64 halves (reuse stage smem); rescale by 1/1024
    float* ts = (float*)smem;
    int qr = lid >> 2, qc = (lid & 3) * 2;
#pragma unroll 1
    for (int h = 0; h < 2; h++) {
        if ((wn >> 1) == h) {
#pragma unroll
            for (int mt = 0; mt < 4; mt++)
#pragma unroll
                for (int nt = 0; nt < 4; nt++)
#pragma unroll
                    for (int d = 0; d < 4; d++) {
                        int r = wm * 64 + mt * 16 + qr + (d >> 1) * 8;
                        int lc = (wn & 1) * 32 + nt * 8 + qc + (d & 1);
                        float v = fmaxf(acc[mt][nt][d] * 9.765625e-4f, 0.f);
                        if (bi + r == bj + h * 64 + lc) v = 0.f;
                        ts[r * TS_PAD + lc] = v;
                    }
        }
        __syncthreads();
        {   // direct: 128 rows x 64 cols
            int r = tid >> 1, seg = tid & 1;
            const float4* src = (const float4*)(ts + r * TS_PAD + seg * 32);
            float4* dst = (float4*)(g_S + (size_t)(bi + r) * MTOT + bj + h * 64 + seg * 32);
#pragma unroll
            for (int k = 0; k < 8; k++) dst[k] = src[k];
        }
        {   // mirror: 64 cols -> rows (transposed read)
            int cc = tid >> 2, q = (tid & 3) * 32;
            float4* dst = (float4*)(g_S + (size_t)(bj + h * 64 + cc) * MTOT + bi + q);
#pragma unroll
            for (int k = 0; k < 8; k++) {
                int rr = q + k * 4;
                dst[k] = make_float4(ts[(rr + 0) * TS_PAD + cc], ts[(rr + 1) * TS_PAD + cc],
                                     ts[(rr + 2) * TS_PAD + cc], ts[(rr + 3) * TS_PAD + cc]);
            }
        }
        __syncthreads();
    }
}

// ---------------- per-row exact top-32: single pass, reg-resident (R12 form) ----------------
__global__ __launch_bounds__(256) void topk_kernel() {
    int row = blockIdx.x;
    int tid = threadIdx.x;
    int w = tid >> 5, lane = tid & 31;
    const float4* Sr4 = (const float4*)(g_S + (size_t)row * MTOT);
    unsigned int v[32];
#pragma unroll
    for (int k = 0; k < 8; k++) {
        float4 f = Sr4[tid + (k << 8)];
        v[4 * k + 0] = __float_as_uint(f.x);
        v[4 * k + 1] = __float_as_uint(f.y);
        v[4 * k + 2] = __float_as_uint(f.z);
        v[4 * k + 3] = __float_as_uint(f.w);
    }
    __shared__ int wc[2][8];
    __shared__ int slist_n, s_pos;
    __shared__ unsigned int skth;
    __shared__ unsigned int lval[2048];
    __shared__ int lidx[2048];
    if (tid == 0) { slist_n = 0; s_pos = 0; }
    __syncthreads();
    // coarse bin floor: bits 29..22 (values < 2^30), one barrier per bit
    unsigned int kth = 0;
    for (int bit = 29; bit >= 22; bit--) {
        unsigned int cand = kth | (1u << bit);
        int c = 0;
#pragma unroll
        for (int k = 0; k < 32; k++) c += (v[k] >= cand) ? 1 : 0;
        int wsum = __reduce_add_sync(0xffffffffu, c);
        if (lane == 0) wc[bit & 1][w] = wsum;
        __syncthreads();
        int tot = wc[bit & 1][0] + wc[bit & 1][1] + wc[bit & 1][2] + wc[bit & 1][3] +
                  wc[bit & 1][4] + wc[bit & 1][5] + wc[bit & 1][6] + wc[bit & 1][7];
        if (tot >= 32) kth = cand;
    }
    // compact candidates >= bin floor from registers (no re-read)
#pragma unroll
    for (int k = 0; k < 32; k++) {
        if (v[k] >= kth) {
            int p = atomicAdd(&slist_n, 1);
            if (p < 2048) {
                lval[p] = v[k];
                lidx[p] = 4 * tid + (k >> 2) * 1024 + (k & 3);
            }
        }
    }
    __syncthreads();
    int n = min(slist_n, 2048);
    if (tid < 32) {                            // warp 0: refine bits 21..0 on compact list
        unsigned int kf = kth;
        if (n <= 256) {                        // register-cached fast path
            unsigned int cach[8];
#pragma unroll
            for (int q = 0; q < 8; q++) {
                int e = lane + q * 32;
                cach[q] = (e < n) ? lval[e] : 0u;
            }
            for (int bit = 21; bit >= 0; bit--) {
                unsigned int cand = kf | (1u << bit);
                int c = 0;
#pragma unroll
                for (int q = 0; q < 8; q++) c += (cach[q] >= cand) ? 1 : 0;
                c = __reduce_add_sync(0xffffffffu, c);
                if (c >= 32) kf = cand;
            }
        } else {
            for (int bit = 21; bit >= 0; bit--) {
                unsigned int cand = kf | (1u << bit);
                int c = 0;
                for (int e = lane; e < n; e += 32) c += (lval[e] >= cand) ? 1 : 0;
                c = __reduce_add_sync(0xffffffffu, c);
                if (c >= 32) kf = cand;
            }
        }
        if (tid == 0) skth = kf;
    }
    __syncthreads();
    unsigned int kf = skth;
    for (int e = tid; e < n; e += 256) {
        if (lval[e] >= kf) {
            int p = atomicAdd(&s_pos, 1);
            if (p < 32) {
                int j = lidx[e];
                float fv = __uint_as_float(lval[e]);
                g_topi[(row << 5) + p] = j;
                g_topv[(row << 5) + p] = fv;
                atomicAdd(&g_rowsumA[j], 0.5f * fv);
                atomicAdd(&g_rowsumA[row], 0.5f * fv);
                atomicAdd(&g_tcnt[j], 1);
            }
        }
    }
}

// ---------------- exclusive scan of transpose counts (1 block) ----------------
__global__ __launch_bounds__(1024) void scan_kernel() {
    __shared__ int ssum[1024];
    int tid = threadIdx.x;
    int local[8], s = 0;
#pragma unroll
    for (int k = 0; k < 8; k++) { local[k] = g_tcnt[tid * 8 + k]; s += local[k]; }
    ssum[tid] = s;
    __syncthreads();
    int acc = s;
    for (int off = 1; off < 1024; off <<= 1) {
        int vv = (tid >= off) ? ssum[tid - off] : 0;
        __syncthreads();
        acc += vv;
        ssum[tid] = acc;
        __syncthreads();
    }
    int run = acc - s;
#pragma unroll
    for (int k = 0; k < 8; k++) {
        g_toff[tid * 8 + k] = run;
        g_tfill[tid * 8 + k] = run;
        run += local[k];
    }
    if (tid == 1023) g_toff[MTOT] = run;
}

__global__ void fill_kernel() {
    int idx = blockIdx.x * 256 + threadIdx.x;
    int j = g_topi[idx];
    int pos = atomicAdd(&g_tfill[j], 1);
    g_tadj[pos] = idx;
}

// ---------------- pixel kNN: one warp per pixel ----------------
__global__ __launch_bounds__(256) void pixknn_kernel(const float* __restrict__ im) {
    int w = threadIdx.x >> 5, lane = threadIdx.x & 31;
    int p = blockIdx.x * 8 + w;
    int cfg = blockIdx.y;
    int b = blockIdx.z;
    float dw = (cfg == 0) ? 2.0f : 0.1f;
    __shared__ float sR[HW], sG[HW], sB[HW], sX[HW], sY[HW], sQ[HW];
    int tid = threadIdx.x;
    const float* imb = im + (size_t)b * 3 * HW;
    for (int q = tid; q < HW; q += 256) {
        float r = (imb[q] + 1.f) * 0.5f;
        float g = (imb[HW + q] + 1.f) * 0.5f;
        float bl = (imb[2 * HW + q] + 1.f) * 0.5f;
        float x = ((float)(q & 31) / 31.0f) * dw;
        float y = ((float)(q >> 5) / 31.0f) * dw;
        sR[q] = r; sG[q] = g; sB[q] = bl; sX[q] = x; sY[q] = y;
        sQ[q] = r * r + g * g + bl * bl + x * x + y * y;
    }
    __syncthreads();
    float rp = sR[p], gp = sG[p], bp = sB[p], xp = sX[p], yp = sY[p], qp = sQ[p];
    unsigned int key[32];
#pragma unroll
    for (int k = 0; k < 32; k++) {
        int q = lane + (k << 5);
        float dot = rp * sR[q] + gp * sG[q] + bp * sB[q] + xp * sX[q] + yp * sY[q];
        float d2 = fmaxf(qp + sQ[q] - 2.f * dot, 0.f);
        key[k] = (q == p) ? 0x7F800000u : __float_as_uint(d2);
    }
    unsigned int s = 0;
    for (int bit = 30; bit >= 0; bit--) {
        unsigned int cand = s | (1u << bit);
        int c = 0;
#pragma unroll
        for (int k = 0; k < 32; k++) c += (key[k] < cand) ? 1 : 0;
        int tot = __reduce_add_sync(0xffffffffu, c);
        if (tot <= 9) s = cand;
    }
    size_t rbase = ((size_t)b * HW + p) * HW;
#pragma unroll
    for (int k = 0; k < 32; k++) {
        if (key[k] <= s) {
            int q = lane + (k << 5);
            g_A2[rbase + q] = 1;
            g_A2[((size_t)b * HW + q) * HW + p] = 1;
        }
    }
}

// ---------------- pixel degree + feature degree (merged) ----------------
__global__ __launch_bounds__(256) void d2_kernel() {
    int r = blockIdx.x;
    const unsigned int* row = (const unsigned int*)(g_A2 + (size_t)r * HW);
    int tid = threadIdx.x;
    unsigned int u = row[tid];
    int c = (u & 0xFF) + ((u >> 8) & 0xFF) + ((u >> 16) & 0xFF) + (u >> 24);
    int wsum = __reduce_add_sync(0xffffffffu, c);
    __shared__ int wc[8];
    if ((tid & 31) == 0) wc[tid >> 5] = wsum;
    __syncthreads();
    if (tid == 0) {
        int tot = wc[0] + wc[1] + wc[2] + wc[3] + wc[4] + wc[5] + wc[6] + wc[7];
        g_D2inv[r] = 1.0f / sqrtf((float)tot);
        g_Dinv[r] = 1.0f / sqrtf(g_rowsumA[r]);
    }
}

// ---------------- feature gram @ Psi: pure gather via transpose CSR ----------------
__global__ __launch_bounds__(64) void gpfeat_kernel() {
    int j = blockIdx.x;
    int c = threadIdx.x;
    __shared__ int sidx[512];
    __shared__ float sw[512];
    float dj = g_Dinv[j];
    if (c < 32) {
        int t = g_topi[(j << 5) + c];
        sidx[c] = t;
        sw[c] = 0.5f * g_topv[(j << 5) + c] * dj * g_Dinv[t];
    }
    __syncthreads();
    float acc = 0.f;
#pragma unroll
    for (int e = 0; e < 32; e++) acc += sw[e] * g_Psi[sidx[e] * KD + c];
    __syncthreads();
    int start = g_toff[j], end = g_toff[j + 1];
    for (int ch = start; ch < end; ch += 512) {
        int n = min(512, end - ch);
        for (int k = c; k < n; k += 64) {
            int idx = g_tadj[ch + k];
            int i = idx >> 5;
            sidx[k] = i;
            sw[k] = 0.5f * g_topv[idx] * dj * g_Dinv[i];
        }
        __syncthreads();
        for (int k = 0; k < n; k++) acc += sw[k] * g_Psi[sidx[k] * KD + c];
        __syncthreads();
    }
    g_gP[j * KD + c] = acc;
}

// ---------------- pixel gram @ Psi (block diagonal) ----------------
__global__ __launch_bounds__(128) void gppix_kernel() {
    int i = blockIdx.x;
    int b = i >> 10;
    __shared__ int lst[1024];
    __shared__ int cnt;
    __shared__ float part[64];
    int tid = threadIdx.x;
    if (tid == 0) cnt = 0;
    __syncthreads();
    const unsigned char* row = g_A2 + (size_t)i * HW;
    for (int q = tid; q < HW; q += 128) {
        if (row[q]) { int pos = atomicAdd(&cnt, 1); lst[pos] = q; }
    }
    __syncthreads();
    int n = cnt;
    float w0 = 0.05f * g_D2inv[i];
    int col = tid & 63, half = tid >> 6;
    float acc = 0.f;
    for (int e = half; e < n; e += 2) {
        int gq = (b << 10) + lst[e];
        acc += g_D2inv[gq] * g_Psi[gq * KD + col];
    }
    if (half) part[col] = acc;
    __syncthreads();
    if (!half) {
        float tot = (acc + part[col]) * w0;
        g_gP[i * KD + col] += tot;
    }
}

// ---------------- R = Psi_s^T @ gP ----------------
__global__ __launch_bounds__(256) void r_kernel() {
    __shared__ float sp[64][KD];
    __shared__ float sg[64][KD];
    int i0 = blockIdx.x * 64;
    int tid = threadIdx.x;
    for (int e = tid; e < 64 * KD; e += 256) {
        sp[e >> 6][e & 63] = g_Psi[(i0 + (e >> 6)) * KD + (e & 63)];
        sg[e >> 6][e & 63] = g_gP[(i0 + (e >> 6)) * KD + (e & 63)];
    }
    __syncthreads();
    int a = tid >> 2;
    int c0 = (tid & 3) << 4;
    float acc[16];
#pragma unroll
    for (int u = 0; u < 16; u++) acc[u] = 0.f;
    for (int ii = 0; ii < 64; ii++) {
        float pa = sp[ii][a];
#pragma unroll
        for (int u = 0; u < 16; u++) acc[u] += pa * sg[ii][c0 + u];
    }
#pragma unroll
    for (int u = 0; u < 16; u++) atomicAdd(&g_R[a * KD + c0 + u], acc[u]);
}

// ---------------- loss & reg ----------------
__global__ __launch_bounds__(64) void final_kernel(float* __restrict__ out) {
    int tid = threadIdx.x;
    float tr = 0.f, rg = 0.f;
    for (int e = tid; e < KD * KD; e += 64) {
        float v = g_R[e];
        int a = e >> 6, b = e & 63;
        if (a == b) tr += v;
        if (b > a) rg += v * v;
    }
#pragma unroll
    for (int o = 16; o; o >>= 1) {
        tr += __shfl_xor_sync(0xffffffffu, tr, o);
        rg += __shfl_xor_sync(0xffffffffu, rg, o);
    }
    __shared__ float st[2], sr2[2];
    if ((tid & 31) == 0) { st[tid >> 5] = tr; sr2[tid >> 5] = rg; }
    __syncthreads();
    if (tid == 0) {
        out[0] = -(st[0] + st[1]) / 64.0f;
        out[1] = (sr2[0] + sr2[1]) / 64.0f;
    }
}

extern "C" void kernel_launch(void* const* d_in, const int* in_sizes, int n_in,
                              void* d_out, int out_size) {
    const float* hf = (const float*)d_in[0];   // (8,1024,768)
    const float* psi = (const float*)d_in[1];  // (8,1024,64)
    const float* im = (const float*)d_in[2];   // (8,3,32,32)
    float* out = (float*)d_out;

    cudaFuncSetAttribute(gemm_mma_kernel, cudaFuncAttributeMaxDynamicSharedMemorySize,
                         SMEM_TOTAL);

    prep_kernel<<<2048, 256>>>(psi);
    norm_kernel<<<MTOT, 256>>>(hf);

    dim3 g(MTOT / 128, MTOT / 128);
    gemm_mma_kernel<<<g, 256, SMEM_TOTAL>>>();

    topk_kernel<<<MTOT, 256>>>();
    scan_kernel<<<1, 1024>>>();
    fill_kernel<<<NEDGE / 256, 256>>>();
    pixknn_kernel<<<dim3(HW / 8, 2, BSZ), 256>>>(im);
    d2_kernel<<<MTOT, 256>>>();

    gpfeat_kernel<<<MTOT, 64>>>();
    gppix_kernel<<<MTOT, 128>>>();

    r_kernel<<<MTOT / 64, 256>>>();
    final_kernel<<<1, 64>>>(out);
}

// round 15
// speedup vs baseline: 1.0608x; 1.0108x over previous
#include <cuda_runtime.h>
#include <cuda_fp16.h>
#include <math.h>
#include <stdint.h>

#define MTOT 8192
#define DF   768
#define KD   64
#define HW   1024
#define BSZ  8
#define NEDGE (MTOT * 32)

// ---------------- scratch (device globals; no allocation) ----------------
__device__ uint4 g_Xhi4[MTOT * DF / 8];            // fp16 hi parts (x*32)
__device__ uint4 g_Xlo4[MTOT * DF / 8];            // fp16 lo parts
__device__ float g_S[(size_t)MTOT * MTOT];         // 256 MB similarity matrix
__device__ float g_Psi[MTOT * KD];
__device__ float g_topv[NEDGE];
__device__ int   g_topi[NEDGE];
__device__ float g_rowsumA[MTOT];
__device__ float g_Dinv[MTOT];
__device__ unsigned char g_A2[(size_t)MTOT * HW];
__device__ float g_D2inv[MTOT];
__device__ float g_gP[MTOT * KD];
__device__ float g_R[KD * KD];
__device__ int   g_tcnt[MTOT];
__device__ int   g_toff[MTOT + 1];
__device__ int   g_tfill[MTOT];
__device__ int   g_tadj[NEDGE];

// ---------------- helpers ----------------
__device__ __forceinline__ uint32_t smem_u32(const void* p) {
    uint32_t a;
    asm("{ .reg .u64 t; cvta.to.shared.u64 t, %1; cvt.u32.u64 %0, t; }" : "=r"(a) : "l"(p));
    return a;
}
#define SWZ(o) ((o) ^ (((o) >> 3) & 0x70))

__device__ __forceinline__ void ldmx4(uint32_t* r, uint32_t addr) {
    asm volatile("ldmatrix.sync.aligned.m8n8.x4.shared.b16 {%0,%1,%2,%3}, [%4];"
                 : "=r"(r[0]), "=r"(r[1]), "=r"(r[2]), "=r"(r[3]) : "r"(addr));
}
__device__ __forceinline__ void mma_f16(float* d, const uint32_t* a, uint32_t b0, uint32_t b1) {
    asm volatile(
        "mma.sync.aligned.m16n8k16.row.col.f32.f16.f16.f32 "
        "{%0,%1,%2,%3}, {%4,%5,%6,%7}, {%8,%9}, {%0,%1,%2,%3};"
        : "+f"(d[0]), "+f"(d[1]), "+f"(d[2]), "+f"(d[3])
        : "r"(a[0]), "r"(a[1]), "r"(a[2]), "r"(a[3]), "r"(b0), "r"(b1));
}
__device__ __forceinline__ void cp_async16(uint32_t dst, const void* src) {
    asm volatile("cp.async.cg.shared.global [%0], [%1], 16;" :: "r"(dst), "l"(src));
}
#define CP_COMMIT() asm volatile("cp.async.commit_group;" ::: "memory")
#define CP_WAIT(n)  asm volatile("cp.async.wait_group %0;" :: "n"(n) : "memory")

// GEMM (R8 tiling): CTA 128x128, 8 warps 2(M)x4(N), warp tile 64x32, K-chunk 32.
// fp16 3-product split (x scaled by 32): S*1024 = hi*hi + lo*hi + hi*lo
// Stage = 4 tiles (Ahi,Alo,Bhi,Blo) x 8KB = 32KB; 3 stages = 96KB; 2 CTAs/SM.
#define STG        32768
#define SMEM_TOTAL (3 * STG)
#define TS_PAD     68
#define NCHUNK     (DF / 32)   // 24

// ---------------- zero scratch + psi scale (merged) ----------------
__global__ void prep_kernel(const float* __restrict__ psi) {
    int idx = blockIdx.x * blockDim.x + threadIdx.x;
    int stride = gridDim.x * blockDim.x;
    for (int i = idx; i < MTOT; i += stride) { g_rowsumA[i] = 0.f; g_tcnt[i] = 0; }
    for (int i = idx; i < KD * KD; i += stride) g_R[i] = 0.f;
    for (int i = idx; i < MTOT * KD; i += stride)
        g_Psi[i] = psi[i] * 3.16227766016837933f;   // sqrt(10)
    unsigned int* a2 = (unsigned int*)g_A2;
    for (int i = idx; i < (MTOT * HW) >> 2; i += stride) a2[i] = 0u;
}

// ---------------- row L2-normalize + scaled fp16 hi/lo split ----------------
__global__ __launch_bounds__(256) void norm_kernel(const float* __restrict__ hf) {
    int row = blockIdx.x;
    const float* x = hf + (size_t)row * DF;
    int tid = threadIdx.x;
    float s = 0.f;
    for (int d = tid; d < DF; d += 256) { float v = x[d]; s += v * v; }
#pragma unroll
    for (int o = 16; o; o >>= 1) s += __shfl_xor_sync(0xffffffffu, s, o);
    __shared__ float red[8];
    if ((tid & 31) == 0) red[tid >> 5] = s;
    __syncthreads();
    float tot = red[0] + red[1] + red[2] + red[3] + red[4] + red[5] + red[6] + red[7];
    float inv = 32.0f / sqrtf(tot);            // x * 32 (avoids fp16 denormal lo)
    __half* hi = (__half*)g_Xhi4;
    __half* lo = (__half*)g_Xlo4;
    for (int d = tid; d < DF; d += 256) {
        float v = x[d] * inv;
        __half h = __float2half_rn(v);
        float hr = __half2float(h);
        hi[(size_t)row * DF + d] = h;
        lo[(size_t)row * DF + d] = __float2half_rn(v - hr);
    }
}

// ---------------- HMMA GEMM: S = Xn Xn^T (proven R8/R11/R14 form) ----------------
__global__ __launch_bounds__(256, 2) void gemm_mma_kernel() {
    int bi = blockIdx.y << 7;
    int bj = blockIdx.x << 7;
    if (bj < bi) return;                       // symmetry: upper block triangle only
    extern __shared__ __align__(1024) char smem[];
    uint32_t sb = smem_u32(smem);
    int tid = threadIdx.x;
    int wid = tid >> 5, lid = tid & 31;
    int wm = wid >> 2, wn = wid & 3;           // warp grid 2(M) x 4(N), tile 64x32

    float acc[4][4][4];
#pragma unroll
    for (int mt = 0; mt < 4; mt++)
#pragma unroll
        for (int nt = 0; nt < 4; nt++)
#pragma unroll
            for (int d = 0; d < 4; d++) acc[mt][nt][d] = 0.f;

    int arow = lid & 15, acb = lid >> 4;
    int brow = (lid >= 16 ? 8 : 0) + (lid & 7);
    int bcb = (lid >> 3) & 1;

    auto rpoff = [](int row, int c16) -> uint32_t {
        uint32_t o = (uint32_t)((row >> 1) * 128 + (row & 1) * 64 + c16 * 16);
        return SWZ(o);
    };

    auto load_chunk = [&](int c, int buf) {
        uint32_t base = sb + buf * STG;
#pragma unroll
        for (int i = 0; i < 8; i++) {
            int id = i * 256 + tid;            // 0..2047
            int t = id >> 9, rem = id & 511;   // tile, then 128 rows x 4 cb
            int row = rem >> 2, cb = rem & 3;
            const uint4* gs = (t & 1) ? g_Xlo4 : g_Xhi4;
            int rb = (t < 2) ? bi : bj;
            cp_async16(base + t * 8192 + rpoff(row, cb),
                       gs + (size_t)(rb + row) * (DF / 8) + c * 4 + cb);
        }
        CP_COMMIT();
    };

    load_chunk(0, 0);
    load_chunk(1, 1);
#pragma unroll 1
    for (int c = 0; c < NCHUNK; c++) {
        if (c + 1 < NCHUNK) { CP_WAIT(1); } else { CP_WAIT(0); }
        __syncthreads();
        if (c + 2 < NCHUNK) load_chunk(c + 2, (c + 2) % 3);
        uint32_t st = sb + (c % 3) * STG;
        uint32_t Ahi = st, Alo = st + 8192, Bhi = st + 16384, Blo = st + 24576;
#pragma unroll
        for (int kk = 0; kk < 2; kk++) {
            int ac16 = kk * 2 + acb;
            int bc16 = kk * 2 + bcb;
            uint32_t ahf[4][4], bhf[2][4];
#pragma unroll
            for (int mt = 0; mt < 4; mt++)
                ldmx4(ahf[mt], Ahi + rpoff(wm * 64 + mt * 16 + arow, ac16));
#pragma unroll
            for (int pt = 0; pt < 2; pt++)
                ldmx4(bhf[pt], Bhi + rpoff(wn * 32 + pt * 16 + brow, bc16));
            // hi x hi
#pragma unroll
            for (int mt = 0; mt < 4; mt++)
#pragma unroll
                for (int nt = 0; nt < 4; nt++)
                    mma_f16(acc[mt][nt], ahf[mt],
                            bhf[nt >> 1][(nt & 1) * 2], bhf[nt >> 1][(nt & 1) * 2 + 1]);
            // lo x hi (reuse bhf)
            {
                uint32_t alf[4][4];
#pragma unroll
                for (int mt = 0; mt < 4; mt++)
                    ldmx4(alf[mt], Alo + rpoff(wm * 64 + mt * 16 + arow, ac16));
#pragma unroll
                for (int mt = 0; mt < 4; mt++)
#pragma unroll
                    for (int nt = 0; nt < 4; nt++)
                        mma_f16(acc[mt][nt], alf[mt],
                                bhf[nt >> 1][(nt & 1) * 2], bhf[nt >> 1][(nt & 1) * 2 + 1]);
            }
            // hi x lo (reuse ahf)
            {
                uint32_t blf[2][4];
#pragma unroll
                for (int pt = 0; pt < 2; pt++)
                    ldmx4(blf[pt], Blo + rpoff(wn * 32 + pt * 16 + brow, bc16));
#pragma unroll
                for (int mt = 0; mt < 4; mt++)
#pragma unroll
                    for (int nt = 0; nt < 4; nt++)
                        mma_f16(acc[mt][nt], ahf[mt],
                                blf[nt >> 1][(nt & 1) * 2], blf[nt >> 1][(nt & 1) * 2 + 1]);
            }
        }
    }
    __syncthreads();

    // epilogue in two 128x64 halves (reuse stage smem); rescale by 1/1024
    float* ts = (float*)smem;
    int qr = lid >> 2, qc = (lid & 3) * 2;
#pragma unroll 1
    for (int h = 0; h < 2; h++) {
        if ((wn >> 1) == h) {
#pragma unroll
            for (int mt = 0; mt < 4; mt++)
#pragma unroll
                for (int nt = 0; nt < 4; nt++)
#pragma unroll
                    for (int d = 0; d < 4; d++) {
                        int r = wm * 64 + mt * 16 + qr + (d >> 1) * 8;
                        int lc = (wn & 1) * 32 + nt * 8 + qc + (d & 1);
                        float v = fmaxf(acc[mt][nt][d] * 9.765625e-4f, 0.f);
                        if (bi + r == bj + h * 64 + lc) v = 0.f;
                        ts[r * TS_PAD + lc] = v;
                    }
        }
        __syncthreads();
        {   // direct: 128 rows x 64 cols
            int r = tid >> 1, seg = tid & 1;
            const float4* src = (const float4*)(ts + r * TS_PAD + seg * 32);
            float4* dst = (float4*)(g_S + (size_t)(bi + r) * MTOT + bj + h * 64 + seg * 32);
#pragma unroll
            for (int k = 0; k < 8; k++) dst[k] = src[k];
        }
        {   // mirror: 64 cols -> rows (transposed read)
            int cc = tid >> 2, q = (tid & 3) * 32;
            float4* dst = (float4*)(g_S + (size_t)(bj + h * 64 + cc) * MTOT + bi + q);
#pragma unroll
            for (int k = 0; k < 8; k++) {
                int rr = q + k * 4;
                dst[k] = make_float4(ts[(rr + 0) * TS_PAD + cc], ts[(rr + 1) * TS_PAD + cc],
                                     ts[(rr + 2) * TS_PAD + cc], ts[(rr + 3) * TS_PAD + cc]);
            }
        }
        __syncthreads();
    }
}

// ---------------- per-row exact top-32: single pass + per-thread max-skip ----------------
__global__ __launch_bounds__(256) void topk_kernel() {
    int row = blockIdx.x;
    int tid = threadIdx.x;
    int w = tid >> 5, lane = tid & 31;
    const float4* Sr4 = (const float4*)(g_S + (size_t)row * MTOT);
    unsigned int v[32];
    unsigned int m = 0;                        // per-thread max (monotone skip key)
#pragma unroll
    for (int k = 0; k < 8; k++) {
        float4 f = Sr4[tid + (k << 8)];
        v[4 * k + 0] = __float_as_uint(f.x);
        v[4 * k + 1] = __float_as_uint(f.y);
        v[4 * k + 2] = __float_as_uint(f.z);
        v[4 * k + 3] = __float_as_uint(f.w);
        m = max(m, max(max(v[4 * k + 0], v[4 * k + 1]), max(v[4 * k + 2], v[4 * k + 3])));
    }
    __shared__ int wc[2][8];
    __shared__ int slist_n, s_pos;
    __shared__ unsigned int skth;
    __shared__ unsigned int lval[2048];
    __shared__ int lidx[2048];
    if (tid == 0) { slist_n = 0; s_pos = 0; }
    __syncthreads();
    // coarse bin floor: bits 29..22, one barrier per bit; skip threads whose max < cand
    unsigned int kth = 0;
    for (int bit = 29; bit >= 22; bit--) {
        unsigned int cand = kth | (1u << bit);
        int c = 0;
        if (m >= cand) {
#pragma unroll
            for (int k = 0; k < 32; k++) c += (v[k] >= cand) ? 1 : 0;
        }
        int wsum = __reduce_add_sync(0xffffffffu, c);
        if (lane == 0) wc[bit & 1][w] = wsum;
        __syncthreads();
        int tot = wc[bit & 1][0] + wc[bit & 1][1] + wc[bit & 1][2] + wc[bit & 1][3] +
                  wc[bit & 1][4] + wc[bit & 1][5] + wc[bit & 1][6] + wc[bit & 1][7];
        if (tot >= 32) kth = cand;
    }
    // compact candidates >= bin floor from registers (max-skip guarded)
    if (m >= kth) {
#pragma unroll
        for (int k = 0; k < 32; k++) {
            if (v[k] >= kth) {
                int p = atomicAdd(&slist_n, 1);
                if (p < 2048) {
                    lval[p] = v[k];
                    lidx[p] = 4 * tid + (k >> 2) * 1024 + (k & 3);
                }
            }
        }
    }
    __syncthreads();
    int n = min(slist_n, 2048);
    if (tid < 32) {                            // warp 0: refine bits 21..0 on compact list
        unsigned int kf = kth;
        if (n <= 256) {                        // register-cached fast path
            unsigned int cach[8];
#pragma unroll
            for (int q = 0; q < 8; q++) {
                int e = lane + q * 32;
                cach[q] = (e < n) ? lval[e] : 0u;
            }
            for (int bit = 21; bit >= 0; bit--) {
                unsigned int cand = kf | (1u << bit);
                int c = 0;
#pragma unroll
                for (int q = 0; q < 8; q++) c += (cach[q] >= cand) ? 1 : 0;
                c = __reduce_add_sync(0xffffffffu, c);
                if (c >= 32) kf = cand;
            }
        } else {
            for (int bit = 21; bit >= 0; bit--) {
                unsigned int cand = kf | (1u << bit);
                int c = 0;
                for (int e = lane; e < n; e += 32) c += (lval[e] >= cand) ? 1 : 0;
                c = __reduce_add_sync(0xffffffffu, c);
                if (c >= 32) kf = cand;
            }
        }
        if (tid == 0) skth = kf;
    }
    __syncthreads();
    unsigned int kf = skth;
    for (int e = tid; e < n; e += 256) {
        if (lval[e] >= kf) {
            int p = atomicAdd(&s_pos, 1);
            if (p < 32) {
                int j = lidx[e];
                float fv = __uint_as_float(lval[e]);
                g_topi[(row << 5) + p] = j;
                g_topv[(row << 5) + p] = fv;
                atomicAdd(&g_rowsumA[j], 0.5f * fv);
                atomicAdd(&g_rowsumA[row], 0.5f * fv);
                atomicAdd(&g_tcnt[j], 1);
            }
        }
    }
}

// ---------------- exclusive scan of transpose counts (1 block) ----------------
__global__ __launch_bounds__(1024) void scan_kernel() {
    __shared__ int ssum[1024];
    int tid = threadIdx.x;
    int local[8], s = 0;
#pragma unroll
    for (int k = 0; k < 8; k++) { local[k] = g_tcnt[tid * 8 + k]; s += local[k]; }
    ssum[tid] = s;
    __syncthreads();
    int acc = s;
    for (int off = 1; off < 1024; off <<= 1) {
        int vv = (tid >= off) ? ssum[tid - off] : 0;
        __syncthreads();
        acc += vv;
        ssum[tid] = acc;
        __syncthreads();
    }
    int run = acc - s;
#pragma unroll
    for (int k = 0; k < 8; k++) {
        g_toff[tid * 8 + k] = run;
        g_tfill[tid * 8 + k] = run;
        run += local[k];
    }
    if (tid == 1023) g_toff[MTOT] = run;
}

__global__ void fill_kernel() {
    int idx = blockIdx.x * 256 + threadIdx.x;
    int j = g_topi[idx];
    int pos = atomicAdd(&g_tfill[j], 1);
    g_tadj[pos] = idx;
}

// ---------------- pixel kNN: one warp per pixel ----------------
__global__ __launch_bounds__(256) void pixknn_kernel(const float* __restrict__ im) {
    int w = threadIdx.x >> 5, lane = threadIdx.x & 31;
    int p = blockIdx.x * 8 + w;
    int cfg = blockIdx.y;
    int b = blockIdx.z;
    float dw = (cfg == 0) ? 2.0f : 0.1f;
    __shared__ float sR[HW], sG[HW], sB[HW], sX[HW], sY[HW], sQ[HW];
    int tid = threadIdx.x;
    const float* imb = im + (size_t)b * 3 * HW;
    for (int q = tid; q < HW; q += 256) {
        float r = (imb[q] + 1.f) * 0.5f;
        float g = (imb[HW + q] + 1.f) * 0.5f;
        float bl = (imb[2 * HW + q] + 1.f) * 0.5f;
        float x = ((float)(q & 31) / 31.0f) * dw;
        float y = ((float)(q >> 5) / 31.0f) * dw;
        sR[q] = r; sG[q] = g; sB[q] = bl; sX[q] = x; sY[q] = y;
        sQ[q] = r * r + g * g + bl * bl + x * x + y * y;
    }
    __syncthreads();
    float rp = sR[p], gp = sG[p], bp = sB[p], xp = sX[p], yp = sY[p], qp = sQ[p];
    unsigned int key[32];
#pragma unroll
    for (int k = 0; k < 32; k++) {
        int q = lane + (k << 5);
        float dot = rp * sR[q] + gp * sG[q] + bp * sB[q] + xp * sX[q] + yp * sY[q];
        float d2 = fmaxf(qp + sQ[q] - 2.f * dot, 0.f);
        key[k] = (q == p) ? 0x7F800000u : __float_as_uint(d2);
    }
    unsigned int s = 0;
    for (int bit = 30; bit >= 0; bit--) {
        unsigned int cand = s | (1u << bit);
        int c = 0;
#pragma unroll
        for (int k = 0; k < 32; k++) c += (key[k] < cand) ? 1 : 0;
        int tot = __reduce_add_sync(0xffffffffu, c);
        if (tot <= 9) s = cand;
    }
    size_t rbase = ((size_t)b * HW + p) * HW;
#pragma unroll
    for (int k = 0; k < 32; k++) {
        if (key[k] <= s) {
            int q = lane + (k << 5);
            g_A2[rbase + q] = 1;
            g_A2[((size_t)b * HW + q) * HW + p] = 1;
        }
    }
}

// ---------------- pixel degree + feature degree (merged) ----------------
__global__ __launch_bounds__(256) void d2_kernel() {
    int r = blockIdx.x;
    const unsigned int* row = (const unsigned int*)(g_A2 + (size_t)r * HW);
    int tid = threadIdx.x;
    unsigned int u = row[tid];
    int c = (u & 0xFF) + ((u >> 8) & 0xFF) + ((u >> 16) & 0xFF) + (u >> 24);
    int wsum = __reduce_add_sync(0xffffffffu, c);
    __shared__ int wc[8];
    if ((tid & 31) == 0) wc[tid >> 5] = wsum;
    __syncthreads();
    if (tid == 0) {
        int tot = wc[0] + wc[1] + wc[2] + wc[3] + wc[4] + wc[5] + wc[6] + wc[7];
        g_D2inv[r] = 1.0f / sqrtf((float)tot);
        g_Dinv[r] = 1.0f / sqrtf(g_rowsumA[r]);
    }
}

// ---------------- feature gram @ Psi: pure gather via transpose CSR ----------------
__global__ __launch_bounds__(64) void gpfeat_kernel() {
    int j = blockIdx.x;
    int c = threadIdx.x;
    __shared__ int sidx[512];
    __shared__ float sw[512];
    float dj = g_Dinv[j];
    if (c < 32) {
        int t = g_topi[(j << 5) + c];
        sidx[c] = t;
        sw[c] = 0.5f * g_topv[(j << 5) + c] * dj * g_Dinv[t];
    }
    __syncthreads();
    float acc = 0.f;
#pragma unroll
    for (int e = 0; e < 32; e++) acc += sw[e] * g_Psi[sidx[e] * KD + c];
    __syncthreads();
    int start = g_toff[j], end = g_toff[j + 1];
    for (int ch = start; ch < end; ch += 512) {
        int n = min(512, end - ch);
        for (int k = c; k < n; k += 64) {
            int idx = g_tadj[ch + k];
            int i = idx >> 5;
            sidx[k] = i;
            sw[k] = 0.5f * g_topv[idx] * dj * g_Dinv[i];
        }
        __syncthreads();
        for (int k = 0; k < n; k++) acc += sw[k] * g_Psi[sidx[k] * KD + c];
        __syncthreads();
    }
    g_gP[j * KD + c] = acc;
}

// ---------------- pixel gram @ Psi (block diagonal) ----------------
__global__ __launch_bounds__(128) void gppix_kernel() {
    int i = blockIdx.x;
    int b = i >> 10;
    __shared__ int lst[1024];
    __shared__ int cnt;
    __shared__ float part[64];
    int tid = threadIdx.x;
    if (tid == 0) cnt = 0;
    __syncthreads();
    const unsigned char* row = g_A2 + (size_t)i * HW;
    for (int q = tid; q < HW; q += 128) {
        if (row[q]) { int pos = atomicAdd(&cnt, 1); lst[pos] = q; }
    }
    __syncthreads();
    int n = cnt;
    float w0 = 0.05f * g_D2inv[i];
    int col = tid & 63, half = tid >> 6;
    float acc = 0.f;
    for (int e = half; e < n; e += 2) {
        int gq = (b << 10) + lst[e];
        acc += g_D2inv[gq] * g_Psi[gq * KD + col];
    }
    if (half) part[col] = acc;
    __syncthreads();
    if (!half) {
        float tot = (acc + part[col]) * w0;
        g_gP[i * KD + col] += tot;
    }
}

// ---------------- R = Psi_s^T @ gP ----------------
__global__ __launch_bounds__(256) void r_kernel() {
    __shared__ float sp[64][KD];
    __shared__ float sg[64][KD];
    int i0 = blockIdx.x * 64;
    int tid = threadIdx.x;
    for (int e = tid; e < 64 * KD; e += 256) {
        sp[e >> 6][e & 63] = g_Psi[(i0 + (e >> 6)) * KD + (e & 63)];
        sg[e >> 6][e & 63] = g_gP[(i0 + (e >> 6)) * KD + (e & 63)];
    }
    __syncthreads();
    int a = tid >> 2;
    int c0 = (tid & 3) << 4;
    float acc[16];
#pragma unroll
    for (int u = 0; u < 16; u++) acc[u] = 0.f;
    for (int ii = 0; ii < 64; ii++) {
        float pa = sp[ii][a];
#pragma unroll
        for (int u = 0; u < 16; u++) acc[u] += pa * sg[ii][c0 + u];
    }
#pragma unroll
    for (int u = 0; u < 16; u++) atomicAdd(&g_R[a * KD + c0 + u], acc[u]);
}

// ---------------- loss & reg ----------------
__global__ __launch_bounds__(64) void final_kernel(float* __restrict__ out) {
    int tid = threadIdx.x;
    float tr = 0.f, rg = 0.f;
    for (int e = tid; e < KD * KD; e += 64) {
        float v = g_R[e];
        int a = e >> 6, b = e & 63;
        if (a == b) tr += v;
        if (b > a) rg += v * v;
    }
#pragma unroll
    for (int o = 16; o; o >>= 1) {
        tr += __shfl_xor_sync(0xffffffffu, tr, o);
        rg += __shfl_xor_sync(0xffffffffu, rg, o);
    }
    __shared__ float st[2], sr2[2];
    if ((tid & 31) == 0) { st[tid >> 5] = tr; sr2[tid >> 5] = rg; }
    __syncthreads();
    if (tid == 0) {
        out[0] = -(st[0] + st[1]) / 64.0f;
        out[1] = (sr2[0] + sr2[1]) / 64.0f;
    }
}

extern "C" void kernel_launch(void* const* d_in, const int* in_sizes, int n_in,
                              void* d_out, int out_size) {
    const float* hf = (const float*)d_in[0];   // (8,1024,768)
    const float* psi = (const float*)d_in[1];  // (8,1024,64)
    const float* im = (const float*)d_in[2];   // (8,3,32,32)
    float* out = (float*)d_out;

    cudaFuncSetAttribute(gemm_mma_kernel, cudaFuncAttributeMaxDynamicSharedMemorySize,
                         SMEM_TOTAL);

    prep_kernel<<<2048, 256>>>(psi);
    norm_kernel<<<MTOT, 256>>>(hf);

    dim3 g(MTOT / 128, MTOT / 128);
    gemm_mma_kernel<<<g, 256, SMEM_TOTAL>>>();

    topk_kernel<<<MTOT, 256>>>();
    scan_kernel<<<1, 1024>>>();
    fill_kernel<<<NEDGE / 256, 256>>>();
    pixknn_kernel<<<dim3(HW / 8, 2, BSZ), 256>>>(im);
    d2_kernel<<<MTOT, 256>>>();

    gpfeat_kernel<<<MTOT, 64>>>();
    gppix_kernel<<<MTOT, 128>>>();

    r_kernel<<<MTOT / 64, 256>>>();
    final_kernel<<<1, 64>>>(out);
}